// round 9
// baseline (speedup 1.0000x reference)
#include <cuda_runtime.h>
#include <cstdint>

// out[i, b*O + o] = input[b, i] * exp(weight[i, o]) + bias[i, o]
// I = 512, O = 128, B = 2048. Output fp32, 512 MB -> store-bound.
//
// R9 vs R8 (74.0us, DRAM=79.3%): double-buffered TMA drain.
// Each CTA produces 128 batches (64KB contiguous output) as 4 x 16KB
// sub-tiles through a 2 x 16KB SMEM double buffer: while sub-tile s-1 is
// being bulk-stored (cp.async.bulk SMEM->GMEM, L1-bypass, L2::evict_first),
// sub-tile s is computed into the other buffer. wait_group.read 1 gates
// buffer reuse. Keeps the per-SM TMA stream continuously fed instead of
// relying purely on cross-CTA overlap.

#define I_FEATS    512
#define O_FEATS    128
#define BATCH      2048
#define B_PER_CTA  128                        // batches per CTA (64KB out)
#define NSUB       4                          // sub-tiles per CTA
#define B_SUB      (B_PER_CTA / NSUB)         // 32 batches per sub-tile
#define SUB_ELEMS  (B_SUB * O_FEATS)          // 4096 floats = 16KB
#define SUB_BYTES  (SUB_ELEMS * 4)
#define NCHUNK     (BATCH / B_PER_CTA)        // 16
#define KPW        (B_SUB / 8)                // 4 batches per warp per sub-tile

__global__ void __launch_bounds__(256)
linear_nosum_tma_db_kernel(const float* __restrict__ input,
                           const float* __restrict__ weight,
                           const float* __restrict__ bias,
                           float* __restrict__ out)
{
    __shared__ alignas(128) float buf[2][SUB_ELEMS];   // 2 x 16KB

    const int i     = blockIdx.y;            // feature row 0..511
    const int chunk = blockIdx.x;            // batch chunk 0..15
    const int warp  = threadIdx.x >> 5;      // 0..7
    const int lane  = threadIdx.x & 31;      // 0..31
    const int o     = lane << 2;             // output column base

    // Per-row constants: exp(weight[i, o..o+3]) and bias[i, o..o+3]
    const float4 w4 = *reinterpret_cast<const float4*>(weight + i * O_FEATS + o);
    const float4 b4 = *reinterpret_cast<const float4*>(bias   + i * O_FEATS + o);
    const float e0 = expf(w4.x);
    const float e1 = expf(w4.y);
    const float e2 = expf(w4.z);
    const float e3 = expf(w4.w);

    // Front-load all 16 input scalars this warp needs (4 per sub-tile).
    const int bbase = chunk * B_PER_CTA + warp;
    const float* __restrict__ in_ptr = input + (size_t)bbase * I_FEATS + i;
    float xs[NSUB][KPW];
#pragma unroll
    for (int s = 0; s < NSUB; s++)
#pragma unroll
        for (int k = 0; k < KPW; k++)
            xs[s][k] = __ldg(in_ptr + (size_t)(s * B_SUB + (k << 3)) * I_FEATS);

    float* gbase = out + (size_t)i * ((size_t)BATCH * O_FEATS)
                       + (size_t)chunk * (B_PER_CTA * O_FEATS);

    uint64_t pol;
    asm("createpolicy.fractional.L2::evict_first.b64 %0, 1.0;" : "=l"(pol));

#pragma unroll
    for (int s = 0; s < NSUB; s++) {
        // Before refilling buf[s&1], the bulk read issued at sub-tile s-2
        // must have completed (allow <=1 group still in flight).
        if (s >= 2 && threadIdx.x == 0)
            asm volatile("cp.async.bulk.wait_group.read 1;" ::: "memory");
        __syncthreads();                      // buffer-free visible to all

        float* b = buf[s & 1];
#pragma unroll
        for (int k = 0; k < KPW; k++) {
            const float x = xs[s][k];
            float4 r;
            r.x = fmaf(x, e0, b4.x);
            r.y = fmaf(x, e1, b4.y);
            r.z = fmaf(x, e2, b4.z);
            r.w = fmaf(x, e3, b4.w);
            *reinterpret_cast<float4*>(b + (warp + (k << 3)) * O_FEATS + o) = r;
        }
        __syncthreads();                      // STS complete before bulk read

        if (threadIdx.x == 0) {
            uint32_t saddr;
            asm("{ .reg .u64 t; cvta.to.shared.u64 t, %1; cvt.u32.u64 %0, t; }"
                : "=r"(saddr) : "l"(b));
            asm volatile("fence.proxy.async.shared::cta;" ::: "memory");
            asm volatile(
                "cp.async.bulk.global.shared::cta.bulk_group.L2::cache_hint "
                "[%0], [%1], %2, %3;"
                :: "l"(gbase + (size_t)s * SUB_ELEMS), "r"(saddr),
                   "r"((uint32_t)SUB_BYTES), "l"(pol)
                : "memory");
            asm volatile("cp.async.bulk.commit_group;" ::: "memory");
        }
    }

    // Drain: SMEM must stay alive until the last bulk read finishes.
    if (threadIdx.x == 0)
        asm volatile("cp.async.bulk.wait_group.read 0;" ::: "memory");
    __syncthreads();
}

extern "C" void kernel_launch(void* const* d_in, const int* in_sizes, int n_in,
                              void* d_out, int out_size)
{
    const float* input  = (const float*)d_in[0];
    const float* weight = (const float*)d_in[1];
    const float* bias   = (const float*)d_in[2];
    float* out = (float*)d_out;

    dim3 grid(NCHUNK, I_FEATS);   // (16, 512) = 8192 CTAs
    dim3 block(256);
    linear_nosum_tma_db_kernel<<<grid, block>>>(input, weight, bias, out);
}

// round 10
// speedup vs baseline: 1.0328x; 1.0328x over previous
#include <cuda_runtime.h>
#include <cstdint>

// out[i, b*O + o] = input[b, i] * exp(weight[i, o]) + bias[i, o]
// I = 512, O = 128, B = 2048. Output fp32, 512 MB -> store-bound.
//
// R10 vs R8 (74.0us, DRAM=79.3%, occ=70%): same single-buffer SMEM->TMA
// bulk-store structure (the R9 double-buffer was a regression: DRAM% flat,
// pure barrier overhead), but 16KB tiles instead of 32KB:
//   grid (64,512)=32768 CTAs, 256 thr, smem 16KB -> occ ~100% (8 CTAs/SM),
//   8 concurrent bulk-store streams per SM + smoother wave tails.
// Probes whether the 79% DRAM plateau is concurrency-limited or the HBM
// pure-write ceiling.

#define I_FEATS    512
#define O_FEATS    128
#define BATCH      2048
#define B_PER_CTA  32                         // batches per CTA tile
#define NCHUNK     (BATCH / B_PER_CTA)        // 64
#define KPW        (B_PER_CTA / 8)            // 4 batches per warp
#define TILE_ELEMS (B_PER_CTA * O_FEATS)      // 4096 floats
#define TILE_BYTES (TILE_ELEMS * 4)           // 16 KB

__global__ void __launch_bounds__(256)
linear_nosum_tma16_kernel(const float* __restrict__ input,
                          const float* __restrict__ weight,
                          const float* __restrict__ bias,
                          float* __restrict__ out)
{
    __shared__ alignas(128) float buf[TILE_ELEMS];   // 16 KB static

    const int i     = blockIdx.y;            // feature row 0..511
    const int chunk = blockIdx.x;            // batch chunk 0..63
    const int warp  = threadIdx.x >> 5;      // 0..7
    const int lane  = threadIdx.x & 31;      // 0..31
    const int o     = lane << 2;             // output column base

    // Per-row constants: exp(weight[i, o..o+3]) and bias[i, o..o+3]
    const float4 w4 = *reinterpret_cast<const float4*>(weight + i * O_FEATS + o);
    const float4 b4 = *reinterpret_cast<const float4*>(bias   + i * O_FEATS + o);
    const float e0 = expf(w4.x);
    const float e1 = expf(w4.y);
    const float e2 = expf(w4.z);
    const float e3 = expf(w4.w);

    const int b0 = chunk * B_PER_CTA + warp; // this warp's first batch
    const float* __restrict__ in_ptr = input + (size_t)b0 * I_FEATS + i;

    // Front-batch the 4 strided input scalars (MLP=4 hides DRAM latency).
    float xs[KPW];
#pragma unroll
    for (int k = 0; k < KPW; k++)
        xs[k] = __ldg(in_ptr + (size_t)(k << 3) * I_FEATS);

    // Fill the SMEM tile: warp writes 512B contiguous per batch (STS.128).
#pragma unroll
    for (int k = 0; k < KPW; k++) {
        const float x = xs[k];
        float4 r;
        r.x = fmaf(x, e0, b4.x);
        r.y = fmaf(x, e1, b4.y);
        r.z = fmaf(x, e2, b4.z);
        r.w = fmaf(x, e3, b4.w);
        *reinterpret_cast<float4*>(buf + (warp + (k << 3)) * O_FEATS + o) = r;
    }
    __syncthreads();

    // One 16KB bulk TMA store of the contiguous tile (L1-bypass, L2 evict-first).
    if (threadIdx.x == 0) {
        uint32_t saddr;
        asm("{ .reg .u64 t; cvta.to.shared.u64 t, %1; cvt.u32.u64 %0, t; }"
            : "=r"(saddr) : "l"(buf));
        float* g = out + (size_t)i * ((size_t)BATCH * O_FEATS)
                       + (size_t)chunk * TILE_ELEMS;
        uint64_t pol;
        asm("createpolicy.fractional.L2::evict_first.b64 %0, 1.0;" : "=l"(pol));
        asm volatile("fence.proxy.async.shared::cta;" ::: "memory");
        asm volatile(
            "cp.async.bulk.global.shared::cta.bulk_group.L2::cache_hint "
            "[%0], [%1], %2, %3;"
            :: "l"(g), "r"(saddr), "r"((uint32_t)TILE_BYTES), "l"(pol)
            : "memory");
        asm volatile("cp.async.bulk.commit_group;" ::: "memory");
        // SMEM must outlive the bulk read.
        asm volatile("cp.async.bulk.wait_group.read 0;" ::: "memory");
    }
    __syncthreads();
}

extern "C" void kernel_launch(void* const* d_in, const int* in_sizes, int n_in,
                              void* d_out, int out_size)
{
    const float* input  = (const float*)d_in[0];
    const float* weight = (const float*)d_in[1];
    const float* bias   = (const float*)d_in[2];
    float* out = (float*)d_out;

    dim3 grid(NCHUNK, I_FEATS);   // (64, 512) = 32768 CTAs
    dim3 block(256);
    linear_nosum_tma16_kernel<<<grid, block>>>(input, weight, bias, out);
}